// round 9
// baseline (speedup 1.0000x reference)
#include <cuda_runtime.h>

// ---------------- problem constants ----------------
#define B_    32
#define N_    10000
#define FIN_  64
#define FOUT_ 64
#define FC_   128                 // concat feature dim (inputs | hx)
#define E_    160000
#define KD_   3
#define M_    (N_ * B_)           // 320000 GEMM rows
#define NBF_  (N_ * B_ * FC_)     // 40,960,000 floats per X buffer
#define CH_   4                   // conv chunk passes (keeps 41MB gather set in L2)

// ---------------- device scratch (no allocs allowed) ----------------
__device__ float g_x0[NBF_];      // X layout: [node][batch][128]
__device__ float g_x1[NBF_];
__device__ float g_x2[NBF_];
__device__ float g_zr[NBF_];      // sigmoid gates: [node][batch][z(64)|r(64)]
__device__ int   g_rowptr[N_ + 1];
__device__ int   g_rowcur[N_];
__device__ int   g_colidx[E_];
__device__ float g_wsrt[E_];
__device__ int   g_is32;          // 1 if edge_index is int32, 0 if int64

// ---------------- f32x2 packed-FMA helpers (Blackwell FFMA2) ----------------
__device__ __forceinline__ unsigned long long pk2(float x, float y) {
    unsigned long long r;
    asm("mov.b64 %0, {%1, %2};" : "=l"(r) : "f"(x), "f"(y));
    return r;
}
__device__ __forceinline__ void upk2(unsigned long long p, float& x, float& y) {
    asm("mov.b64 {%0, %1}, %2;" : "=f"(x), "=f"(y) : "l"(p));
}
__device__ __forceinline__ void ffma2(unsigned long long& d, unsigned long long a,
                                      unsigned long long b) {
    asm("fma.rn.f32x2 %0, %1, %2, %0;" : "+l"(d) : "l"(a), "l"(b));
}

// ---------------- edge_index dtype detection ----------------
// JAX with x64 disabled silently downcasts jnp.int64 -> int32. Detect which
// dtype the harness actually gave us. Reading 64 int64 = 512B is in-bounds
// for either dtype (int32 buffer is 1.28MB). If data is genuinely int64,
// every value lies in [0, N_). If it's int32, each int64 read combines two
// random node ids: high word nonzero with P ~ (1 - 1e-4) per element.
__global__ void detect_kernel(const long long* __restrict__ ei) {
    if (threadIdx.x == 0 && blockIdx.x == 0) {
        int is32 = 0;
        for (int e = 0; e < 64; ++e) {
            long long v = ei[e];
            if (v < 0 || v >= (long long)N_) { is32 = 1; break; }
        }
        g_is32 = is32;
    }
}

__device__ __forceinline__ int edge_at(const void* eiv, int idx) {
    if (g_is32) return ((const int*)eiv)[idx];
    return (int)((const long long*)eiv)[idx];
}

// ---------------- CSR construction ----------------
__global__ void zero_counts_kernel() {
    int i = blockIdx.x * blockDim.x + threadIdx.x;
    if (i < N_) g_rowcur[i] = 0;
}

__global__ void hist_kernel(const void* __restrict__ eiv) {
    int e = blockIdx.x * blockDim.x + threadIdx.x;
    if (e < E_) {
        int r = edge_at(eiv, e);                       // ei[0..E) = row
        atomicAdd(&g_rowcur[r], 1);
    }
}

// single-block exclusive scan over 10000 counts
__global__ void scan_kernel() {
    __shared__ int sm[1024];
    int offset = 0;
    for (int base = 0; base < N_; base += 1024) {
        int i = base + threadIdx.x;
        int v = (i < N_) ? g_rowcur[i] : 0;
        sm[threadIdx.x] = v;
        __syncthreads();
        #pragma unroll
        for (int d = 1; d < 1024; d <<= 1) {
            int t = (threadIdx.x >= (unsigned)d) ? sm[threadIdx.x - d] : 0;
            __syncthreads();
            sm[threadIdx.x] += t;
            __syncthreads();
        }
        if (i < N_) {
            int excl = offset + sm[threadIdx.x] - v;
            g_rowptr[i] = excl;
            g_rowcur[i] = excl;
        }
        offset += sm[1023];
        __syncthreads();
    }
    if (threadIdx.x == 0) g_rowptr[N_] = offset;
}

__global__ void scatter_kernel(const void* __restrict__ eiv,
                               const float* __restrict__ ew) {
    int e = blockIdx.x * blockDim.x + threadIdx.x;
    if (e < E_) {
        int r = edge_at(eiv, e);
        int c = edge_at(eiv, E_ + e);
        int pos = atomicAdd(&g_rowcur[r], 1);
        g_colidx[pos] = c;
        g_wsrt[pos]   = ew[e];
    }
}

// ---------------- X construction ----------------
// X[n][b][f] = f<64 ? inputs[b][n][f] : hx[b][n][f-64]
__global__ void build_x_kernel(const float4* __restrict__ inp,
                               const float4* __restrict__ hxv) {
    int idx = blockIdx.x * blockDim.x + threadIdx.x;   // float4 index, NBF_/4 total
    if (idx >= NBF_ / 4) return;
    int n   = idx >> 10;
    int rem = idx & 1023;
    int b   = rem >> 5;
    int fq  = rem & 31;                                // float4 within 128 feats
    size_t src = ((size_t)b * N_ + n) * 16;
    float4 v;
    if (fq < 16) v = inp[src + fq];
    else         v = hxv[src + (fq - 16)];
    reinterpret_cast<float4*>(g_x0)[idx] = v;
}

// X_cand[n][b][f] = f<64 ? inputs : r*hx   (r = gates[...,64:128])
__global__ void build_xcand_kernel(const float4* __restrict__ inp,
                                   const float4* __restrict__ hxv) {
    int idx = blockIdx.x * blockDim.x + threadIdx.x;
    if (idx >= NBF_ / 4) return;
    int n   = idx >> 10;
    int rem = idx & 1023;
    int b   = rem >> 5;
    int fq  = rem & 31;
    size_t src = ((size_t)b * N_ + n) * 16;
    float4 v;
    if (fq < 16) {
        v = inp[src + fq];
    } else {
        float4 h = hxv[src + (fq - 16)];
        // zr row has 32 float4; r occupies [16,32) which equals fq here
        float4 r = reinterpret_cast<const float4*>(g_zr)[(size_t)(n * B_ + b) * 32 + fq];
        v = make_float4(h.x * r.x, h.y * r.y, h.z * r.z, h.w * r.w);
    }
    reinterpret_cast<float4*>(g_x0)[idx] = v;
}

// ---------------- graph conv (CSR gather, chunked for L2 residency) ----------------
// mode 0: g_x1 = conv(g_x0)
// mode 1: g_x2 = 2*conv(g_x1) - g_x0
__global__ void __launch_bounds__(256) conv_kernel(int mode) {
    const float4* __restrict__ X;
    const float4* __restrict__ Xs = nullptr;
    float4* __restrict__ Y;
    if (mode == 0) {
        X = reinterpret_cast<const float4*>(g_x0);
        Y = reinterpret_cast<float4*>(g_x1);
    } else {
        X  = reinterpret_cast<const float4*>(g_x1);
        Xs = reinterpret_cast<const float4*>(g_x0);
        Y  = reinterpret_cast<float4*>(g_x2);
    }
    int n   = blockIdx.x;
    int off = blockIdx.y * 256 + threadIdx.x;   // float4 index within node slab [0,1024)

    float4 acc = make_float4(0.f, 0.f, 0.f, 0.f);
    int js = g_rowptr[n], je = g_rowptr[n + 1];
    int j = js;
    #pragma unroll 1
    for (; j + 1 < je; j += 2) {
        int   c0 = g_colidx[j];     float w0 = g_wsrt[j];
        int   c1 = g_colidx[j + 1]; float w1 = g_wsrt[j + 1];
        float4 u = __ldg(&X[(size_t)c0 * 1024 + off]);
        float4 v = __ldg(&X[(size_t)c1 * 1024 + off]);
        acc.x = fmaf(w0, u.x, fmaf(w1, v.x, acc.x));
        acc.y = fmaf(w0, u.y, fmaf(w1, v.y, acc.y));
        acc.z = fmaf(w0, u.z, fmaf(w1, v.z, acc.z));
        acc.w = fmaf(w0, u.w, fmaf(w1, v.w, acc.w));
    }
    if (j < je) {
        int   c0 = g_colidx[j]; float w0 = g_wsrt[j];
        float4 u = __ldg(&X[(size_t)c0 * 1024 + off]);
        acc.x = fmaf(w0, u.x, acc.x);
        acc.y = fmaf(w0, u.y, acc.y);
        acc.z = fmaf(w0, u.z, acc.z);
        acc.w = fmaf(w0, u.w, acc.w);
    }
    size_t o = (size_t)n * 1024 + off;
    if (mode == 0) {
        Y[o] = acc;
    } else {
        float4 s = Xs[o];
        Y[o] = make_float4(2.f * acc.x - s.x, 2.f * acc.y - s.y,
                           2.f * acc.z - s.z, 2.f * acc.w - s.w);
    }
}

// ---------------- fused GEMM + epilogue ----------------
// A (M x 384) lives in the three slices g_x0|g_x1|g_x2 (each row-contiguous 128).
// W is (TN x 384) row-major.  MODE 0: gates -> sigmoid -> g_zr (TN=128)
// MODE 1: cand -> tanh, out = (1-z)*hx + z*cand (TN=64), output layout (B,N,64).
template <int TN, int MODE>
__global__ void __launch_bounds__(256) gemm_kernel(const float* __restrict__ W,
                                                   const float* __restrict__ bias,
                                                   const float* __restrict__ hx,
                                                   float* __restrict__ out) {
    constexpr int TM = 128, TK = 16;
    constexpr int RM = 8;
    constexpr int RN = TN / 16;      // 8 (gates) or 4 (cand)
    __shared__ float As[TK][TM + 4];
    __shared__ float Bs[TK][TN + 4];

    const int tid = threadIdx.x;
    const int tx  = tid & 15;
    const int ty  = tid >> 4;
    const int m0  = blockIdx.x * TM;

    unsigned long long acc[RM][RN / 2];
    #pragma unroll
    for (int i = 0; i < RM; ++i)
        #pragma unroll
        for (int jj = 0; jj < RN / 2; ++jj) acc[i][jj] = 0ull;

    const float* const slices[3] = {g_x0, g_x1, g_x2};

    #pragma unroll 1
    for (int s = 0; s < 3; ++s) {
        const float* __restrict__ A = slices[s];
        #pragma unroll 1
        for (int kt = 0; kt < FC_; kt += TK) {
            // load A tile: TM x TK
            #pragma unroll
            for (int l = 0; l < (TM * TK) / 256; ++l) {
                int idx = tid + l * 256;
                int m = idx >> 4, k = idx & 15;
                As[k][m] = A[(size_t)(m0 + m) * FC_ + kt + k];
            }
            // load B tile: TN x TK  (Bs[k][n])
            #pragma unroll
            for (int l = 0; l < (TN * TK) / 256; ++l) {
                int idx = tid + l * 256;
                int nn = idx >> 4, k = idx & 15;
                Bs[k][nn] = W[(size_t)nn * (KD_ * FC_) + s * FC_ + kt + k];
            }
            __syncthreads();
            #pragma unroll
            for (int k = 0; k < TK; ++k) {
                float4 av0 = *reinterpret_cast<const float4*>(&As[k][ty * RM]);
                float4 av1 = *reinterpret_cast<const float4*>(&As[k][ty * RM + 4]);
                float a[RM] = {av0.x, av0.y, av0.z, av0.w, av1.x, av1.y, av1.z, av1.w};
                unsigned long long bp[RN / 2];
                #pragma unroll
                for (int jj = 0; jj < RN / 2; ++jj)
                    bp[jj] = *reinterpret_cast<const unsigned long long*>(
                        &Bs[k][tx * RN + 2 * jj]);
                #pragma unroll
                for (int i = 0; i < RM; ++i) {
                    unsigned long long ap = pk2(a[i], a[i]);
                    #pragma unroll
                    for (int jj = 0; jj < RN / 2; ++jj) ffma2(acc[i][jj], ap, bp[jj]);
                }
            }
            __syncthreads();
        }
    }

    // epilogue
    #pragma unroll
    for (int i = 0; i < RM; ++i) {
        int m = m0 + ty * RM + i;
        #pragma unroll
        for (int jj = 0; jj < RN / 2; ++jj) {
            float v0, v1;
            upk2(acc[i][jj], v0, v1);
            int n0 = tx * RN + 2 * jj;
            v0 += bias[n0];
            v1 += bias[n0 + 1];
            if (MODE == 0) {
                g_zr[(size_t)m * FC_ + n0]     = 1.f / (1.f + __expf(-v0));
                g_zr[(size_t)m * FC_ + n0 + 1] = 1.f / (1.f + __expf(-v1));
            } else {
                float c0 = tanhf(v0), c1 = tanhf(v1);
                float z0 = g_zr[(size_t)m * FC_ + n0];
                float z1 = g_zr[(size_t)m * FC_ + n0 + 1];
                int node = m >> 5, b = m & 31;
                size_t o = ((size_t)b * N_ + node) * FOUT_ + n0;
                float h0 = hx[o], h1 = hx[o + 1];
                out[o]     = (1.f - z0) * h0 + z0 * c0;
                out[o + 1] = (1.f - z1) * h1 + z1 * c1;
            }
        }
    }
}

// ---------------- launcher ----------------
extern "C" void kernel_launch(void* const* d_in, const int* in_sizes, int n_in,
                              void* d_out, int out_size) {
    const float* inputs = (const float*)d_in[0];
    const float* hx     = (const float*)d_in[1];
    const void*  ei     = d_in[2];              // int32 or int64 — detected on device
    const float* ew     = (const float*)d_in[3];
    const float* wg     = (const float*)d_in[4];
    const float* wc     = (const float*)d_in[5];
    const float* bg     = (const float*)d_in[6];
    const float* bc     = (const float*)d_in[7];
    float*       out    = (float*)d_out;

    // CSR build (recomputed every call — no caching allowed)
    detect_kernel<<<1, 32>>>((const long long*)ei);
    zero_counts_kernel<<<(N_ + 255) / 256, 256>>>();
    hist_kernel<<<(E_ + 255) / 256, 256>>>(ei);
    scan_kernel<<<1, 1024>>>();
    scatter_kernel<<<(E_ + 255) / 256, 256>>>(ei, ew);

    const int bld_blocks = (NBF_ / 4 + 255) / 256;
    dim3 cgrid(N_, CH_);

    // diffusion on [inputs | hx]
    build_x_kernel<<<bld_blocks, 256>>>((const float4*)inputs, (const float4*)hx);
    conv_kernel<<<cgrid, 256>>>(0);
    conv_kernel<<<cgrid, 256>>>(1);
    gemm_kernel<128, 0><<<M_ / 128, 256>>>(wg, bg, nullptr, nullptr);

    // diffusion on [inputs | r*hx]
    build_xcand_kernel<<<bld_blocks, 256>>>((const float4*)inputs, (const float4*)hx);
    conv_kernel<<<cgrid, 256>>>(0);
    conv_kernel<<<cgrid, 256>>>(1);
    gemm_kernel<64, 1><<<M_ / 128, 256>>>(wc, bc, hx, out);
}

// round 10
// speedup vs baseline: 1.0091x; 1.0091x over previous
#include <cuda_runtime.h>

// ---------------- problem constants ----------------
#define B_    32
#define N_    10000
#define FIN_  64
#define FOUT_ 64
#define FC_   128                 // concat feature dim (inputs | hx)
#define E_    160000
#define KD_   3
#define M_    (N_ * B_)           // 320000 GEMM rows
#define NBF_  (N_ * B_ * FC_)     // 40,960,000 floats per X buffer
#define CH_   4                   // conv chunk passes (keeps 41MB gather set in L2)

// ---------------- device scratch (no allocs allowed) ----------------
__device__ float g_x0[NBF_];      // X layout: [node][batch][128]
__device__ float g_x1[NBF_];
__device__ float g_x2[NBF_];
__device__ float g_zr[NBF_];      // sigmoid gates: [node][batch][z(64)|r(64)]
__device__ int   g_rowptr[N_ + 1];
__device__ int   g_rowcur[N_];
__device__ int   g_colidx[E_];
__device__ float g_wsrt[E_];
__device__ int   g_is32;          // 1 if edge_index is int32, 0 if int64

// ---------------- f32x2 packed-FMA helpers (Blackwell FFMA2) ----------------
__device__ __forceinline__ unsigned long long pk2(float x, float y) {
    unsigned long long r;
    asm("mov.b64 %0, {%1, %2};" : "=l"(r) : "f"(x), "f"(y));
    return r;
}
__device__ __forceinline__ void upk2(unsigned long long p, float& x, float& y) {
    asm("mov.b64 {%0, %1}, %2;" : "=f"(x), "=f"(y) : "l"(p));
}
__device__ __forceinline__ void ffma2(unsigned long long& d, unsigned long long a,
                                      unsigned long long b) {
    asm("fma.rn.f32x2 %0, %1, %2, %0;" : "+l"(d) : "l"(a), "l"(b));
}

// ---------------- edge_index dtype detection ----------------
// JAX with x64 disabled silently downcasts jnp.int64 -> int32. Detect which
// dtype the harness actually gave us. Reading 64 int64 = 512B is in-bounds
// for either dtype (int32 buffer is 1.28MB). If data is genuinely int64,
// every value lies in [0, N_). If it's int32, each int64 read combines two
// random node ids: high word nonzero with P ~ (1 - 1e-4) per element.
__global__ void detect_kernel(const long long* __restrict__ ei) {
    if (threadIdx.x == 0 && blockIdx.x == 0) {
        int is32 = 0;
        for (int e = 0; e < 64; ++e) {
            long long v = ei[e];
            if (v < 0 || v >= (long long)N_) { is32 = 1; break; }
        }
        g_is32 = is32;
    }
}

__device__ __forceinline__ int edge_at(const void* eiv, int idx) {
    if (g_is32) return ((const int*)eiv)[idx];
    return (int)((const long long*)eiv)[idx];
}

// ---------------- CSR construction ----------------
__global__ void zero_counts_kernel() {
    int i = blockIdx.x * blockDim.x + threadIdx.x;
    if (i < N_) g_rowcur[i] = 0;
}

__global__ void hist_kernel(const void* __restrict__ eiv) {
    int e = blockIdx.x * blockDim.x + threadIdx.x;
    if (e < E_) {
        int r = edge_at(eiv, e);                       // ei[0..E) = row
        atomicAdd(&g_rowcur[r], 1);
    }
}

// single-block exclusive scan over 10000 counts
__global__ void scan_kernel() {
    __shared__ int sm[1024];
    int offset = 0;
    for (int base = 0; base < N_; base += 1024) {
        int i = base + threadIdx.x;
        int v = (i < N_) ? g_rowcur[i] : 0;
        sm[threadIdx.x] = v;
        __syncthreads();
        #pragma unroll
        for (int d = 1; d < 1024; d <<= 1) {
            int t = (threadIdx.x >= (unsigned)d) ? sm[threadIdx.x - d] : 0;
            __syncthreads();
            sm[threadIdx.x] += t;
            __syncthreads();
        }
        if (i < N_) {
            int excl = offset + sm[threadIdx.x] - v;
            g_rowptr[i] = excl;
            g_rowcur[i] = excl;
        }
        offset += sm[1023];
        __syncthreads();
    }
    if (threadIdx.x == 0) g_rowptr[N_] = offset;
}

__global__ void scatter_kernel(const void* __restrict__ eiv,
                               const float* __restrict__ ew) {
    int e = blockIdx.x * blockDim.x + threadIdx.x;
    if (e < E_) {
        int r = edge_at(eiv, e);
        int c = edge_at(eiv, E_ + e);
        int pos = atomicAdd(&g_rowcur[r], 1);
        g_colidx[pos] = c;
        g_wsrt[pos]   = ew[e];
    }
}

// ---------------- X construction ----------------
// X[n][b][f] = f<64 ? inputs[b][n][f] : hx[b][n][f-64]
__global__ void build_x_kernel(const float4* __restrict__ inp,
                               const float4* __restrict__ hxv) {
    int idx = blockIdx.x * blockDim.x + threadIdx.x;   // float4 index, NBF_/4 total
    if (idx >= NBF_ / 4) return;
    int n   = idx >> 10;
    int rem = idx & 1023;
    int b   = rem >> 5;
    int fq  = rem & 31;                                // float4 within 128 feats
    size_t src = ((size_t)b * N_ + n) * 16;
    float4 v;
    if (fq < 16) v = inp[src + fq];
    else         v = hxv[src + (fq - 16)];
    reinterpret_cast<float4*>(g_x0)[idx] = v;
}

// X_cand[n][b][f] = f<64 ? inputs : r*hx   (r = gates[...,64:128])
__global__ void build_xcand_kernel(const float4* __restrict__ inp,
                                   const float4* __restrict__ hxv) {
    int idx = blockIdx.x * blockDim.x + threadIdx.x;
    if (idx >= NBF_ / 4) return;
    int n   = idx >> 10;
    int rem = idx & 1023;
    int b   = rem >> 5;
    int fq  = rem & 31;
    size_t src = ((size_t)b * N_ + n) * 16;
    float4 v;
    if (fq < 16) {
        v = inp[src + fq];
    } else {
        float4 h = hxv[src + (fq - 16)];
        // zr row has 32 float4; r occupies [16,32) which equals fq here
        float4 r = reinterpret_cast<const float4*>(g_zr)[(size_t)(n * B_ + b) * 32 + fq];
        v = make_float4(h.x * r.x, h.y * r.y, h.z * r.z, h.w * r.w);
    }
    reinterpret_cast<float4*>(g_x0)[idx] = v;
}

// ---------------- graph conv (CSR gather, chunked for L2 residency) ----------------
// mode 0: g_x1 = conv(g_x0)
// mode 1: g_x2 = 2*conv(g_x1) - g_x0
__global__ void __launch_bounds__(256) conv_kernel(int mode) {
    const float4* __restrict__ X;
    const float4* __restrict__ Xs = nullptr;
    float4* __restrict__ Y;
    if (mode == 0) {
        X = reinterpret_cast<const float4*>(g_x0);
        Y = reinterpret_cast<float4*>(g_x1);
    } else {
        X  = reinterpret_cast<const float4*>(g_x1);
        Xs = reinterpret_cast<const float4*>(g_x0);
        Y  = reinterpret_cast<float4*>(g_x2);
    }
    int n   = blockIdx.x;
    int off = blockIdx.y * 256 + threadIdx.x;   // float4 index within node slab [0,1024)

    float4 acc = make_float4(0.f, 0.f, 0.f, 0.f);
    int js = g_rowptr[n], je = g_rowptr[n + 1];
    int j = js;
    #pragma unroll 1
    for (; j + 1 < je; j += 2) {
        int   c0 = g_colidx[j];     float w0 = g_wsrt[j];
        int   c1 = g_colidx[j + 1]; float w1 = g_wsrt[j + 1];
        float4 u = __ldg(&X[(size_t)c0 * 1024 + off]);
        float4 v = __ldg(&X[(size_t)c1 * 1024 + off]);
        acc.x = fmaf(w0, u.x, fmaf(w1, v.x, acc.x));
        acc.y = fmaf(w0, u.y, fmaf(w1, v.y, acc.y));
        acc.z = fmaf(w0, u.z, fmaf(w1, v.z, acc.z));
        acc.w = fmaf(w0, u.w, fmaf(w1, v.w, acc.w));
    }
    if (j < je) {
        int   c0 = g_colidx[j]; float w0 = g_wsrt[j];
        float4 u = __ldg(&X[(size_t)c0 * 1024 + off]);
        acc.x = fmaf(w0, u.x, acc.x);
        acc.y = fmaf(w0, u.y, acc.y);
        acc.z = fmaf(w0, u.z, acc.z);
        acc.w = fmaf(w0, u.w, acc.w);
    }
    size_t o = (size_t)n * 1024 + off;
    if (mode == 0) {
        Y[o] = acc;
    } else {
        float4 s = Xs[o];
        Y[o] = make_float4(2.f * acc.x - s.x, 2.f * acc.y - s.y,
                           2.f * acc.z - s.z, 2.f * acc.w - s.w);
    }
}

// ---------------- fused GEMM + epilogue ----------------
// A (M x 384) lives in the three slices g_x0|g_x1|g_x2 (each row-contiguous 128).
// W is (TN x 384) row-major.  MODE 0: gates -> sigmoid -> g_zr (TN=128)
// MODE 1: cand -> tanh, out = (1-z)*hx + z*cand (TN=64), output layout (B,N,64).
template <int TN, int MODE>
__global__ void __launch_bounds__(256) gemm_kernel(const float* __restrict__ W,
                                                   const float* __restrict__ bias,
                                                   const float* __restrict__ hx,
                                                   float* __restrict__ out) {
    constexpr int TM = 128, TK = 16;
    constexpr int RM = 8;
    constexpr int RN = TN / 16;      // 8 (gates) or 4 (cand)
    __shared__ float As[TK][TM + 4];
    __shared__ float Bs[TK][TN + 4];

    const int tid = threadIdx.x;
    const int tx  = tid & 15;
    const int ty  = tid >> 4;
    const int m0  = blockIdx.x * TM;

    unsigned long long acc[RM][RN / 2];
    #pragma unroll
    for (int i = 0; i < RM; ++i)
        #pragma unroll
        for (int jj = 0; jj < RN / 2; ++jj) acc[i][jj] = 0ull;

    const float* const slices[3] = {g_x0, g_x1, g_x2};

    #pragma unroll 1
    for (int s = 0; s < 3; ++s) {
        const float* __restrict__ A = slices[s];
        #pragma unroll 1
        for (int kt = 0; kt < FC_; kt += TK) {
            // load A tile: TM x TK
            #pragma unroll
            for (int l = 0; l < (TM * TK) / 256; ++l) {
                int idx = tid + l * 256;
                int m = idx >> 4, k = idx & 15;
                As[k][m] = A[(size_t)(m0 + m) * FC_ + kt + k];
            }
            // load B tile: TN x TK  (Bs[k][n])
            #pragma unroll
            for (int l = 0; l < (TN * TK) / 256; ++l) {
                int idx = tid + l * 256;
                int nn = idx >> 4, k = idx & 15;
                Bs[k][nn] = W[(size_t)nn * (KD_ * FC_) + s * FC_ + kt + k];
            }
            __syncthreads();
            #pragma unroll
            for (int k = 0; k < TK; ++k) {
                float4 av0 = *reinterpret_cast<const float4*>(&As[k][ty * RM]);
                float4 av1 = *reinterpret_cast<const float4*>(&As[k][ty * RM + 4]);
                float a[RM] = {av0.x, av0.y, av0.z, av0.w, av1.x, av1.y, av1.z, av1.w};
                unsigned long long bp[RN / 2];
                #pragma unroll
                for (int jj = 0; jj < RN / 2; ++jj)
                    bp[jj] = *reinterpret_cast<const unsigned long long*>(
                        &Bs[k][tx * RN + 2 * jj]);
                #pragma unroll
                for (int i = 0; i < RM; ++i) {
                    unsigned long long ap = pk2(a[i], a[i]);
                    #pragma unroll
                    for (int jj = 0; jj < RN / 2; ++jj) ffma2(acc[i][jj], ap, bp[jj]);
                }
            }
            __syncthreads();
        }
    }

    // epilogue
    #pragma unroll
    for (int i = 0; i < RM; ++i) {
        int m = m0 + ty * RM + i;
        #pragma unroll
        for (int jj = 0; jj < RN / 2; ++jj) {
            float v0, v1;
            upk2(acc[i][jj], v0, v1);
            int n0 = tx * RN + 2 * jj;
            v0 += bias[n0];
            v1 += bias[n0 + 1];
            if (MODE == 0) {
                g_zr[(size_t)m * FC_ + n0]     = 1.f / (1.f + __expf(-v0));
                g_zr[(size_t)m * FC_ + n0 + 1] = 1.f / (1.f + __expf(-v1));
            } else {
                float c0 = tanhf(v0), c1 = tanhf(v1);
                float z0 = g_zr[(size_t)m * FC_ + n0];
                float z1 = g_zr[(size_t)m * FC_ + n0 + 1];
                int node = m >> 5, b = m & 31;
                size_t o = ((size_t)b * N_ + node) * FOUT_ + n0;
                float h0 = hx[o], h1 = hx[o + 1];
                out[o]     = (1.f - z0) * h0 + z0 * c0;
                out[o + 1] = (1.f - z1) * h1 + z1 * c1;
            }
        }
    }
}

// ---------------- launcher ----------------
extern "C" void kernel_launch(void* const* d_in, const int* in_sizes, int n_in,
                              void* d_out, int out_size) {
    const float* inputs = (const float*)d_in[0];
    const float* hx     = (const float*)d_in[1];
    const void*  ei     = d_in[2];              // int32 or int64 — detected on device
    const float* ew     = (const float*)d_in[3];
    const float* wg     = (const float*)d_in[4];
    const float* wc     = (const float*)d_in[5];
    const float* bg     = (const float*)d_in[6];
    const float* bc     = (const float*)d_in[7];
    float*       out    = (float*)d_out;

    // CSR build (recomputed every call — no caching allowed)
    detect_kernel<<<1, 32>>>((const long long*)ei);
    zero_counts_kernel<<<(N_ + 255) / 256, 256>>>();
    hist_kernel<<<(E_ + 255) / 256, 256>>>(ei);
    scan_kernel<<<1, 1024>>>();
    scatter_kernel<<<(E_ + 255) / 256, 256>>>(ei, ew);

    const int bld_blocks = (NBF_ / 4 + 255) / 256;
    dim3 cgrid(N_, CH_);

    // diffusion on [inputs | hx]
    build_x_kernel<<<bld_blocks, 256>>>((const float4*)inputs, (const float4*)hx);
    conv_kernel<<<cgrid, 256>>>(0);
    conv_kernel<<<cgrid, 256>>>(1);
    gemm_kernel<128, 0><<<M_ / 128, 256>>>(wg, bg, nullptr, nullptr);

    // diffusion on [inputs | r*hx]
    build_xcand_kernel<<<bld_blocks, 256>>>((const float4*)inputs, (const float4*)hx);
    conv_kernel<<<cgrid, 256>>>(0);
    conv_kernel<<<cgrid, 256>>>(1);
    gemm_kernel<64, 1><<<M_ / 128, 256>>>(wc, bc, hx, out);
}

// round 13
// speedup vs baseline: 1.0122x; 1.0031x over previous
#include <cuda_runtime.h>

// ---------------- problem constants ----------------
#define B_    32
#define N_    10000
#define FIN_  64
#define FOUT_ 64
#define FC_   128                 // concat feature dim (inputs | hx)
#define E_    160000
#define KD_   3
#define M_    (N_ * B_)           // 320000 GEMM rows
#define NBF_  (N_ * B_ * FC_)     // 40,960,000 floats per X buffer
#define CH_   4                   // conv chunk passes (keeps 41MB gather set in L2)

// ---------------- device scratch (no allocs allowed) ----------------
__device__ float g_x0[NBF_];      // X layout: [node][batch][128]
__device__ float g_x1[NBF_];
__device__ float g_x2[NBF_];
__device__ float g_zr[NBF_];      // sigmoid gates: [node][batch][z(64)|r(64)]
__device__ int   g_rowptr[N_ + 1];
__device__ int   g_rowcur[N_];
__device__ int   g_colidx[E_];
__device__ float g_wsrt[E_];
__device__ int   g_is32;          // 1 if edge_index is int32, 0 if int64

// ---------------- f32x2 packed-FMA helpers (Blackwell FFMA2) ----------------
__device__ __forceinline__ unsigned long long pk2(float x, float y) {
    unsigned long long r;
    asm("mov.b64 %0, {%1, %2};" : "=l"(r) : "f"(x), "f"(y));
    return r;
}
__device__ __forceinline__ void upk2(unsigned long long p, float& x, float& y) {
    asm("mov.b64 {%0, %1}, %2;" : "=f"(x), "=f"(y) : "l"(p));
}
__device__ __forceinline__ void ffma2(unsigned long long& d, unsigned long long a,
                                      unsigned long long b) {
    asm("fma.rn.f32x2 %0, %1, %2, %0;" : "+l"(d) : "l"(a), "l"(b));
}

// ---------------- edge_index dtype detection ----------------
// JAX with x64 disabled silently downcasts jnp.int64 -> int32. Detect which
// dtype the harness actually gave us. Reading 64 int64 = 512B is in-bounds
// for either dtype (int32 buffer is 1.28MB). If data is genuinely int64,
// every value lies in [0, N_). If it's int32, each int64 read combines two
// random node ids: high word nonzero with P ~ (1 - 1e-4) per element.
__global__ void detect_kernel(const long long* __restrict__ ei) {
    if (threadIdx.x == 0 && blockIdx.x == 0) {
        int is32 = 0;
        for (int e = 0; e < 64; ++e) {
            long long v = ei[e];
            if (v < 0 || v >= (long long)N_) { is32 = 1; break; }
        }
        g_is32 = is32;
    }
}

__device__ __forceinline__ int edge_at(const void* eiv, int idx) {
    if (g_is32) return ((const int*)eiv)[idx];
    return (int)((const long long*)eiv)[idx];
}

// ---------------- CSR construction ----------------
__global__ void zero_counts_kernel() {
    int i = blockIdx.x * blockDim.x + threadIdx.x;
    if (i < N_) g_rowcur[i] = 0;
}

__global__ void hist_kernel(const void* __restrict__ eiv) {
    int e = blockIdx.x * blockDim.x + threadIdx.x;
    if (e < E_) {
        int r = edge_at(eiv, e);                       // ei[0..E) = row
        atomicAdd(&g_rowcur[r], 1);
    }
}

// single-block exclusive scan over 10000 counts
__global__ void scan_kernel() {
    __shared__ int sm[1024];
    int offset = 0;
    for (int base = 0; base < N_; base += 1024) {
        int i = base + threadIdx.x;
        int v = (i < N_) ? g_rowcur[i] : 0;
        sm[threadIdx.x] = v;
        __syncthreads();
        #pragma unroll
        for (int d = 1; d < 1024; d <<= 1) {
            int t = (threadIdx.x >= (unsigned)d) ? sm[threadIdx.x - d] : 0;
            __syncthreads();
            sm[threadIdx.x] += t;
            __syncthreads();
        }
        if (i < N_) {
            int excl = offset + sm[threadIdx.x] - v;
            g_rowptr[i] = excl;
            g_rowcur[i] = excl;
        }
        offset += sm[1023];
        __syncthreads();
    }
    if (threadIdx.x == 0) g_rowptr[N_] = offset;
}

__global__ void scatter_kernel(const void* __restrict__ eiv,
                               const float* __restrict__ ew) {
    int e = blockIdx.x * blockDim.x + threadIdx.x;
    if (e < E_) {
        int r = edge_at(eiv, e);
        int c = edge_at(eiv, E_ + e);
        int pos = atomicAdd(&g_rowcur[r], 1);
        g_colidx[pos] = c;
        g_wsrt[pos]   = ew[e];
    }
}

// ---------------- X construction ----------------
// X[n][b][f] = f<64 ? inputs[b][n][f] : hx[b][n][f-64]
__global__ void build_x_kernel(const float4* __restrict__ inp,
                               const float4* __restrict__ hxv) {
    int idx = blockIdx.x * blockDim.x + threadIdx.x;   // float4 index, NBF_/4 total
    if (idx >= NBF_ / 4) return;
    int n   = idx >> 10;
    int rem = idx & 1023;
    int b   = rem >> 5;
    int fq  = rem & 31;                                // float4 within 128 feats
    size_t src = ((size_t)b * N_ + n) * 16;
    float4 v;
    if (fq < 16) v = inp[src + fq];
    else         v = hxv[src + (fq - 16)];
    reinterpret_cast<float4*>(g_x0)[idx] = v;
}

// X_cand[n][b][f] = f<64 ? inputs : r*hx   (r = gates[...,64:128])
__global__ void build_xcand_kernel(const float4* __restrict__ inp,
                                   const float4* __restrict__ hxv) {
    int idx = blockIdx.x * blockDim.x + threadIdx.x;
    if (idx >= NBF_ / 4) return;
    int n   = idx >> 10;
    int rem = idx & 1023;
    int b   = rem >> 5;
    int fq  = rem & 31;
    size_t src = ((size_t)b * N_ + n) * 16;
    float4 v;
    if (fq < 16) {
        v = inp[src + fq];
    } else {
        float4 h = hxv[src + (fq - 16)];
        // zr row has 32 float4; r occupies [16,32) which equals fq here
        float4 r = reinterpret_cast<const float4*>(g_zr)[(size_t)(n * B_ + b) * 32 + fq];
        v = make_float4(h.x * r.x, h.y * r.y, h.z * r.z, h.w * r.w);
    }
    reinterpret_cast<float4*>(g_x0)[idx] = v;
}

// ---------------- graph conv (CSR gather, chunked for L2 residency) ----------------
// mode 0: g_x1 = conv(g_x0)
// mode 1: g_x2 = 2*conv(g_x1) - g_x0
__global__ void __launch_bounds__(256) conv_kernel(int mode) {
    const float4* __restrict__ X;
    const float4* __restrict__ Xs = nullptr;
    float4* __restrict__ Y;
    if (mode == 0) {
        X = reinterpret_cast<const float4*>(g_x0);
        Y = reinterpret_cast<float4*>(g_x1);
    } else {
        X  = reinterpret_cast<const float4*>(g_x1);
        Xs = reinterpret_cast<const float4*>(g_x0);
        Y  = reinterpret_cast<float4*>(g_x2);
    }
    int n   = blockIdx.x;
    int off = blockIdx.y * 256 + threadIdx.x;   // float4 index within node slab [0,1024)

    float4 acc = make_float4(0.f, 0.f, 0.f, 0.f);
    int js = g_rowptr[n], je = g_rowptr[n + 1];
    int j = js;
    #pragma unroll 1
    for (; j + 1 < je; j += 2) {
        int   c0 = g_colidx[j];     float w0 = g_wsrt[j];
        int   c1 = g_colidx[j + 1]; float w1 = g_wsrt[j + 1];
        float4 u = __ldg(&X[(size_t)c0 * 1024 + off]);
        float4 v = __ldg(&X[(size_t)c1 * 1024 + off]);
        acc.x = fmaf(w0, u.x, fmaf(w1, v.x, acc.x));
        acc.y = fmaf(w0, u.y, fmaf(w1, v.y, acc.y));
        acc.z = fmaf(w0, u.z, fmaf(w1, v.z, acc.z));
        acc.w = fmaf(w0, u.w, fmaf(w1, v.w, acc.w));
    }
    if (j < je) {
        int   c0 = g_colidx[j]; float w0 = g_wsrt[j];
        float4 u = __ldg(&X[(size_t)c0 * 1024 + off]);
        acc.x = fmaf(w0, u.x, acc.x);
        acc.y = fmaf(w0, u.y, acc.y);
        acc.z = fmaf(w0, u.z, acc.z);
        acc.w = fmaf(w0, u.w, acc.w);
    }
    size_t o = (size_t)n * 1024 + off;
    if (mode == 0) {
        Y[o] = acc;
    } else {
        float4 s = Xs[o];
        Y[o] = make_float4(2.f * acc.x - s.x, 2.f * acc.y - s.y,
                           2.f * acc.z - s.z, 2.f * acc.w - s.w);
    }
}

// ---------------- fused GEMM + epilogue ----------------
// A (M x 384) lives in the three slices g_x0|g_x1|g_x2 (each row-contiguous 128).
// W is (TN x 384) row-major.  MODE 0: gates -> sigmoid -> g_zr (TN=128)
// MODE 1: cand -> tanh, out = (1-z)*hx + z*cand (TN=64), output layout (B,N,64).
template <int TN, int MODE>
__global__ void __launch_bounds__(256) gemm_kernel(const float* __restrict__ W,
                                                   const float* __restrict__ bias,
                                                   const float* __restrict__ hx,
                                                   float* __restrict__ out) {
    constexpr int TM = 128, TK = 16;
    constexpr int RM = 8;
    constexpr int RN = TN / 16;      // 8 (gates) or 4 (cand)
    __shared__ float As[TK][TM + 4];
    __shared__ float Bs[TK][TN + 4];

    const int tid = threadIdx.x;
    const int tx  = tid & 15;
    const int ty  = tid >> 4;
    const int m0  = blockIdx.x * TM;

    unsigned long long acc[RM][RN / 2];
    #pragma unroll
    for (int i = 0; i < RM; ++i)
        #pragma unroll
        for (int jj = 0; jj < RN / 2; ++jj) acc[i][jj] = 0ull;

    const float* const slices[3] = {g_x0, g_x1, g_x2};

    #pragma unroll 1
    for (int s = 0; s < 3; ++s) {
        const float* __restrict__ A = slices[s];
        #pragma unroll 1
        for (int kt = 0; kt < FC_; kt += TK) {
            // load A tile: TM x TK
            #pragma unroll
            for (int l = 0; l < (TM * TK) / 256; ++l) {
                int idx = tid + l * 256;
                int m = idx >> 4, k = idx & 15;
                As[k][m] = A[(size_t)(m0 + m) * FC_ + kt + k];
            }
            // load B tile: TN x TK  (Bs[k][n])
            #pragma unroll
            for (int l = 0; l < (TN * TK) / 256; ++l) {
                int idx = tid + l * 256;
                int nn = idx >> 4, k = idx & 15;
                Bs[k][nn] = W[(size_t)nn * (KD_ * FC_) + s * FC_ + kt + k];
            }
            __syncthreads();
            #pragma unroll
            for (int k = 0; k < TK; ++k) {
                float4 av0 = *reinterpret_cast<const float4*>(&As[k][ty * RM]);
                float4 av1 = *reinterpret_cast<const float4*>(&As[k][ty * RM + 4]);
                float a[RM] = {av0.x, av0.y, av0.z, av0.w, av1.x, av1.y, av1.z, av1.w};
                unsigned long long bp[RN / 2];
                #pragma unroll
                for (int jj = 0; jj < RN / 2; ++jj)
                    bp[jj] = *reinterpret_cast<const unsigned long long*>(
                        &Bs[k][tx * RN + 2 * jj]);
                #pragma unroll
                for (int i = 0; i < RM; ++i) {
                    unsigned long long ap = pk2(a[i], a[i]);
                    #pragma unroll
                    for (int jj = 0; jj < RN / 2; ++jj) ffma2(acc[i][jj], ap, bp[jj]);
                }
            }
            __syncthreads();
        }
    }

    // epilogue
    #pragma unroll
    for (int i = 0; i < RM; ++i) {
        int m = m0 + ty * RM + i;
        #pragma unroll
        for (int jj = 0; jj < RN / 2; ++jj) {
            float v0, v1;
            upk2(acc[i][jj], v0, v1);
            int n0 = tx * RN + 2 * jj;
            v0 += bias[n0];
            v1 += bias[n0 + 1];
            if (MODE == 0) {
                g_zr[(size_t)m * FC_ + n0]     = 1.f / (1.f + __expf(-v0));
                g_zr[(size_t)m * FC_ + n0 + 1] = 1.f / (1.f + __expf(-v1));
            } else {
                float c0 = tanhf(v0), c1 = tanhf(v1);
                float z0 = g_zr[(size_t)m * FC_ + n0];
                float z1 = g_zr[(size_t)m * FC_ + n0 + 1];
                int node = m >> 5, b = m & 31;
                size_t o = ((size_t)b * N_ + node) * FOUT_ + n0;
                float h0 = hx[o], h1 = hx[o + 1];
                out[o]     = (1.f - z0) * h0 + z0 * c0;
                out[o + 1] = (1.f - z1) * h1 + z1 * c1;
            }
        }
    }
}

// ---------------- launcher ----------------
extern "C" void kernel_launch(void* const* d_in, const int* in_sizes, int n_in,
                              void* d_out, int out_size) {
    const float* inputs = (const float*)d_in[0];
    const float* hx     = (const float*)d_in[1];
    const void*  ei     = d_in[2];              // int32 or int64 — detected on device
    const float* ew     = (const float*)d_in[3];
    const float* wg     = (const float*)d_in[4];
    const float* wc     = (const float*)d_in[5];
    const float* bg     = (const float*)d_in[6];
    const float* bc     = (const float*)d_in[7];
    float*       out    = (float*)d_out;

    // CSR build (recomputed every call — no caching allowed)
    detect_kernel<<<1, 32>>>((const long long*)ei);
    zero_counts_kernel<<<(N_ + 255) / 256, 256>>>();
    hist_kernel<<<(E_ + 255) / 256, 256>>>(ei);
    scan_kernel<<<1, 1024>>>();
    scatter_kernel<<<(E_ + 255) / 256, 256>>>(ei, ew);

    const int bld_blocks = (NBF_ / 4 + 255) / 256;
    dim3 cgrid(N_, CH_);

    // diffusion on [inputs | hx]
    build_x_kernel<<<bld_blocks, 256>>>((const float4*)inputs, (const float4*)hx);
    conv_kernel<<<cgrid, 256>>>(0);
    conv_kernel<<<cgrid, 256>>>(1);
    gemm_kernel<128, 0><<<M_ / 128, 256>>>(wg, bg, nullptr, nullptr);

    // diffusion on [inputs | r*hx]
    build_xcand_kernel<<<bld_blocks, 256>>>((const float4*)inputs, (const float4*)hx);
    conv_kernel<<<cgrid, 256>>>(0);
    conv_kernel<<<cgrid, 256>>>(1);
    gemm_kernel<64, 1><<<M_ / 128, 256>>>(wc, bc, hx, out);
}